// round 5
// baseline (speedup 1.0000x reference)
#include <cuda_runtime.h>

// ---------------------------------------------------------------------------
// LinearMultiheadAttention: x:(4,4096,1024), 16 heads x 64 dim, chunk 128.
// Pipeline: 3 proj GEMMs -> chunk KV partials -> exclusive scan -> scores ->
// chunk outputs -> output GEMM.
//
// ROOT-CAUSE FIX (round 5): __device__ symbols must NOT be passed directly as
// kernel args from host code — that passes the HOST shadow address, which on
// GB300 (ATS, pageableMemoryAccess=1) is silently writable by the GPU, so the
// GEMMs wrote into host BSS while symbol-referencing kernels read device
// zeros. All global-as-argument uses now go through cudaGetSymbolAddress.
// ---------------------------------------------------------------------------

constexpr int Bn   = 4;
constexpr int Sq   = 4096;
constexpr int Dm   = 1024;
constexpr int Hn   = 16;
constexpr int Hd   = 64;
constexpr int Mtot = Bn * Sq;     // 16384
constexpr int Ck   = 128;
constexpr int Nch  = Sq / Ck;     // 32
constexpr int BHn  = Bn * Hn;     // 64

__device__ __align__(16) float g_q[(size_t)Mtot * Dm];
__device__ __align__(16) float g_k[(size_t)Mtot * Dm];
__device__ __align__(16) float g_v[(size_t)Mtot * Dm];
__device__ __align__(16) float g_att[(size_t)Mtot * Dm];
__device__ __align__(16) float g_Sp[(size_t)BHn * Nch * Hd * Hd];
__device__ __align__(16) float g_zp[(size_t)BHn * Nch * Hd];
__device__ __align__(16) float g_sc[(size_t)BHn * Nch * Ck * Ck];
__device__ int g_flag;

// ---------------------------------------------------------------------------
// Diagnostics (cheap insurance; no-ops when pipeline is healthy)
// ---------------------------------------------------------------------------
__global__ void flag_init_k() { if (threadIdx.x == 0) g_flag = 0; }

__global__ void check_k(int code, const float* __restrict__ p)
{
    __shared__ float red[256];
    float s = 0.f;
    for (int i = threadIdx.x; i < 4096; i += 256) s += fabsf(p[i]);
    red[threadIdx.x] = s;
    __syncthreads();
    for (int w = 128; w > 0; w >>= 1) {
        if (threadIdx.x < w) red[threadIdx.x] += red[threadIdx.x + w];
        __syncthreads();
    }
    if (threadIdx.x == 0) {
        const float t = red[0];
        if (!isfinite(t) || t < 1e-8f) atomicCAS(&g_flag, 0, code);
    }
}

__global__ void sig_fill_k(float* __restrict__ out)
{
    const int f = g_flag;
    if (f == 0) return;
    float C = 1.f;
    for (int i = 0; i < f; i++) C *= 10.f;
    const size_t N = (size_t)Mtot * Dm;
    const size_t stride = (size_t)gridDim.x * blockDim.x;
    for (size_t i = (size_t)blockIdx.x * blockDim.x + threadIdx.x; i < N; i += stride)
        out[i] = C;
}

// ---------------------------------------------------------------------------
// GEMM: Y[m,n] = sum_k A[m,k] * W[n,k] + bias[n]
// MODE 0: plain store | MODE 1: phi + permuted [bh][s][hd] | MODE 2: permuted
// 128x128 block, BK=16, 256 threads, 8x8 per-thread tile.
// ---------------------------------------------------------------------------
template <int MODE>
__global__ void __launch_bounds__(256, 2)
gemm_k(const float* __restrict__ A, const float* __restrict__ W,
       const float* __restrict__ bias, float* __restrict__ out)
{
    __shared__ float As[16][128];
    __shared__ float Bs[16][128];

    const int tid = threadIdx.x;
    const int tx  = tid & 15;
    const int ty  = tid >> 4;
    const int bm  = blockIdx.y << 7;
    const int bn  = blockIdx.x << 7;
    const int lr  = tid >> 2;
    const int lc  = (tid & 3) << 2;

    const float* Ap = A + (size_t)(bm + lr) * Dm + lc;
    const float* Wp = W + (size_t)(bn + lr) * Dm + lc;

    float acc[8][8];
#pragma unroll
    for (int i = 0; i < 8; i++)
#pragma unroll
        for (int j = 0; j < 8; j++) acc[i][j] = 0.f;

    for (int k0 = 0; k0 < Dm; k0 += 16) {
        const float4 a0 = *(const float4*)(Ap + k0);
        const float4 a1 = *(const float4*)(Ap + k0 + (size_t)64 * Dm);
        const float4 b0 = *(const float4*)(Wp + k0);
        const float4 b1 = *(const float4*)(Wp + k0 + (size_t)64 * Dm);
        __syncthreads();
        As[lc + 0][lr]      = a0.x; As[lc + 1][lr]      = a0.y;
        As[lc + 2][lr]      = a0.z; As[lc + 3][lr]      = a0.w;
        As[lc + 0][lr + 64] = a1.x; As[lc + 1][lr + 64] = a1.y;
        As[lc + 2][lr + 64] = a1.z; As[lc + 3][lr + 64] = a1.w;
        Bs[lc + 0][lr]      = b0.x; Bs[lc + 1][lr]      = b0.y;
        Bs[lc + 2][lr]      = b0.z; Bs[lc + 3][lr]      = b0.w;
        Bs[lc + 0][lr + 64] = b1.x; Bs[lc + 1][lr + 64] = b1.y;
        Bs[lc + 2][lr + 64] = b1.z; Bs[lc + 3][lr + 64] = b1.w;
        __syncthreads();
#pragma unroll
        for (int kk = 0; kk < 16; kk++) {
            float af[8], bf[8];
            *(float4*)&af[0] = *(const float4*)&As[kk][ty * 8];
            *(float4*)&af[4] = *(const float4*)&As[kk][ty * 8 + 4];
            *(float4*)&bf[0] = *(const float4*)&Bs[kk][tx * 8];
            *(float4*)&bf[4] = *(const float4*)&Bs[kk][tx * 8 + 4];
#pragma unroll
            for (int i = 0; i < 8; i++)
#pragma unroll
                for (int j = 0; j < 8; j++)
                    acc[i][j] = fmaf(af[i], bf[j], acc[i][j]);
        }
    }

    float bv_[8];
#pragma unroll
    for (int j = 0; j < 8; j++) bv_[j] = bias[bn + tx * 8 + j];

#pragma unroll
    for (int i = 0; i < 8; i++) {
        const int m = bm + ty * 8 + i;
        float y[8];
#pragma unroll
        for (int j = 0; j < 8; j++) {
            float t = acc[i][j] + bv_[j];
            if (MODE == 1) t = (t > 0.f) ? (t + 1.f) : __expf(t);
            y[j] = t;
        }
        float* dst;
        if (MODE == 0) {
            dst = out + (size_t)m * Dm + bn + tx * 8;
        } else {
            const int b  = m >> 12;
            const int s  = m & 4095;
            const int n0 = bn + tx * 8;
            const int h  = n0 >> 6;
            const int e0 = n0 & 63;
            dst = out + ((size_t)(b * Hn + h) * Sq + s) * Hd + e0;
        }
        *(float4*)dst       = make_float4(y[0], y[1], y[2], y[3]);
        *(float4*)(dst + 4) = make_float4(y[4], y[5], y[6], y[7]);
    }
}

// ---------------------------------------------------------------------------
// Per-chunk partials: Sp[bh][c][d][e] = sum_t k[t,d] v[t,e];  zp = sum_t k
// (symbols referenced in device code -> true device copies)
// ---------------------------------------------------------------------------
__global__ void __launch_bounds__(256)
chunk_kv_k()
{
    __shared__ float ks[64 * Hd];
    __shared__ float vs[64 * Hd];
    const int c   = blockIdx.x;
    const int bh  = blockIdx.y;
    const int tid = threadIdx.x;
    const size_t base = ((size_t)bh * Sq + (size_t)c * Ck) * Hd;

    const int r  = tid & 63;
    const int j0 = (tid >> 6) << 4;

    float acc[16];
#pragma unroll
    for (int j = 0; j < 16; j++) acc[j] = 0.f;
    float zacc = 0.f;

    for (int half = 0; half < 2; half++) {
        const float4* kg = (const float4*)(g_k + base + (size_t)half * 64 * Hd);
        const float4* vg = (const float4*)(g_v + base + (size_t)half * 64 * Hd);
        __syncthreads();
        for (int i = tid; i < 64 * Hd / 4; i += 256) {
            ((float4*)ks)[i] = kg[i];
            ((float4*)vs)[i] = vg[i];
        }
        __syncthreads();
        for (int t = 0; t < 64; t++) {
            const float kv = ks[t * Hd + r];
            zacc += kv;
#pragma unroll
            for (int j = 0; j < 16; j++)
                acc[j] = fmaf(kv, vs[t * Hd + j0 + j], acc[j]);
        }
    }

    float* Sd = g_Sp + ((size_t)bh * Nch + c) * (Hd * Hd) + r * Hd + j0;
#pragma unroll
    for (int j = 0; j < 16; j++) Sd[j] = acc[j];
    if (tid < Hd) g_zp[((size_t)bh * Nch + c) * Hd + tid] = zacc;
}

// ---------------------------------------------------------------------------
// In-place exclusive prefix over chunks for Sp and zp. grid (BHn).
// ---------------------------------------------------------------------------
__global__ void __launch_bounds__(256)
scan_k()
{
    const int bh = blockIdx.x;
    float* Sb = g_Sp + (size_t)bh * Nch * Hd * Hd;
    for (int e = threadIdx.x; e < Hd * Hd; e += 256) {
        float acc = 0.f;
        for (int c2 = 0; c2 < Nch; c2++) {
            const float v = Sb[(size_t)c2 * Hd * Hd + e];
            Sb[(size_t)c2 * Hd * Hd + e] = acc;
            acc += v;
        }
    }
    if (threadIdx.x < Hd) {
        float* zb = g_zp + (size_t)bh * Nch * Hd + threadIdx.x;
        float acc = 0.f;
        for (int c2 = 0; c2 < Nch; c2++) {
            const float v = zb[(size_t)c2 * Hd];
            zb[(size_t)c2 * Hd] = acc;
            acc += v;
        }
    }
}

// ---------------------------------------------------------------------------
// Masked score tiles. grid (4, Nch, BHn). Tile 3 = fully masked -> zeros.
// ---------------------------------------------------------------------------
__global__ void __launch_bounds__(256)
attn_scores_k()
{
    __shared__ float qT[64][68];
    __shared__ float kT[64][68];
    const int tile = blockIdx.x;
    const int c    = blockIdx.y;
    const int bh   = blockIdx.z;
    const int tid  = threadIdx.x;

    const int lt0 = (tid >> 4) << 2;
    const int lu0 = (tid & 15) << 2;

    if (tile == 3) {
        float* dst = g_sc + (((size_t)bh * Nch + c) * Ck + lt0) * Ck + 64 + lu0;
#pragma unroll
        for (int i = 0; i < 4; i++)
            *(float4*)(dst + (size_t)i * Ck) = make_float4(0.f, 0.f, 0.f, 0.f);
        return;
    }

    const int th = (tile == 0) ? 0 : 1;
    const int uh = (tile == 2) ? 1 : 0;

    const size_t qbase = ((size_t)bh * Sq + (size_t)c * Ck + th * 64) * Hd;
    const size_t kbase = ((size_t)bh * Sq + (size_t)c * Ck + uh * 64) * Hd;

    for (int i = tid; i < 64 * Hd; i += 256) {
        const int t = i >> 6, d = i & 63;
        qT[d][t] = g_q[qbase + i];
        kT[d][t] = g_k[kbase + i];
    }
    __syncthreads();

    float acc[4][4];
#pragma unroll
    for (int i = 0; i < 4; i++)
#pragma unroll
        for (int j = 0; j < 4; j++) acc[i][j] = 0.f;

    for (int d = 0; d < Hd; d++) {
        float a[4], b[4];
        *(float4*)a = *(const float4*)&qT[d][lt0];
        *(float4*)b = *(const float4*)&kT[d][lu0];
#pragma unroll
        for (int i = 0; i < 4; i++)
#pragma unroll
            for (int j = 0; j < 4; j++)
                acc[i][j] = fmaf(a[i], b[j], acc[i][j]);
    }

    const int tg0 = th * 64 + lt0;
    const int ug0 = uh * 64 + lu0;
    float* dst = g_sc + (((size_t)bh * Nch + c) * Ck + tg0) * Ck + ug0;
#pragma unroll
    for (int i = 0; i < 4; i++) {
        float y[4];
#pragma unroll
        for (int j = 0; j < 4; j++)
            y[j] = (ug0 + j <= tg0 + i) ? acc[i][j] : 0.f;
        *(float4*)(dst + (size_t)i * Ck) = make_float4(y[0], y[1], y[2], y[3]);
    }
}

// ---------------------------------------------------------------------------
// Per-chunk output. grid (Nch, BHn), 256 threads, 48KB static smem.
// ---------------------------------------------------------------------------
__global__ void __launch_bounds__(256)
attn_out2_k()
{
    __shared__ float vs[Ck][Hd];
    __shared__ float Sx[Hd][Hd];

    const int c   = blockIdx.x;
    const int bh  = blockIdx.y;
    const int tid = threadIdx.x;
    const size_t base = ((size_t)bh * Sq + (size_t)c * Ck) * Hd;

    {
        const float4* vg = (const float4*)(g_v + base);
        for (int i = tid; i < Ck * Hd / 4; i += 256) ((float4*)vs)[i] = vg[i];
        const float4* sg = (const float4*)(g_Sp + ((size_t)bh * Nch + c) * (Hd * Hd));
        for (int i = tid; i < Hd * Hd / 4; i += 256) ((float4*)Sx)[i] = sg[i];
    }
    __syncthreads();

    const int e0 = (tid & 7) << 3;
    const int t0 = (tid >> 3) << 2;

    float num[4][8];
    float rs[4], qz[4];
#pragma unroll
    for (int i = 0; i < 4; i++) {
        rs[i] = 0.f; qz[i] = 0.f;
#pragma unroll
        for (int j = 0; j < 8; j++) num[i][j] = 0.f;
    }

    const float* scb = g_sc + ((size_t)bh * Nch + c) * Ck * Ck;
    for (int u4 = 0; u4 < Ck; u4 += 4) {
        float4 sv4[4];
#pragma unroll
        for (int i = 0; i < 4; i++)
            sv4[i] = *(const float4*)&scb[(size_t)(t0 + i) * Ck + u4];
#pragma unroll
        for (int uu = 0; uu < 4; uu++) {
            const int u = u4 + uu;
            float vv[8];
            *(float4*)&vv[0] = *(const float4*)&vs[u][e0];
            *(float4*)&vv[4] = *(const float4*)&vs[u][e0 + 4];
#pragma unroll
            for (int i = 0; i < 4; i++) {
                const float s = (uu == 0) ? sv4[i].x : (uu == 1) ? sv4[i].y
                              : (uu == 2) ? sv4[i].z : sv4[i].w;
                rs[i] += s;
#pragma unroll
                for (int j = 0; j < 8; j++)
                    num[i][j] = fmaf(s, vv[j], num[i][j]);
            }
        }
    }

    const float* qb = g_q + base;
    const float* zb = g_zp + ((size_t)bh * Nch + c) * Hd;
    for (int d4 = 0; d4 < Hd; d4 += 4) {
        float4 qv4[4];
#pragma unroll
        for (int i = 0; i < 4; i++)
            qv4[i] = *(const float4*)&qb[(size_t)(t0 + i) * Hd + d4];
        const float4 z4 = *(const float4*)&zb[d4];
#pragma unroll
        for (int dd = 0; dd < 4; dd++) {
            const int d = d4 + dd;
            const float zc = (dd == 0) ? z4.x : (dd == 1) ? z4.y
                           : (dd == 2) ? z4.z : z4.w;
            float sx[8];
            *(float4*)&sx[0] = *(const float4*)&Sx[d][e0];
            *(float4*)&sx[4] = *(const float4*)&Sx[d][e0 + 4];
#pragma unroll
            for (int i = 0; i < 4; i++) {
                const float qv = (dd == 0) ? qv4[i].x : (dd == 1) ? qv4[i].y
                               : (dd == 2) ? qv4[i].z : qv4[i].w;
                qz[i] = fmaf(qv, zc, qz[i]);
#pragma unroll
                for (int j = 0; j < 8; j++)
                    num[i][j] = fmaf(qv, sx[j], num[i][j]);
            }
        }
    }

    const int b = bh >> 4, h = bh & 15;
    float* ob = g_att + ((size_t)b * Sq + (size_t)c * Ck) * Dm + h * Hd + e0;
#pragma unroll
    for (int i = 0; i < 4; i++) {
        const float inv = 1.0f / (rs[i] + qz[i]);
        float* dst = ob + (size_t)(t0 + i) * Dm;
        *(float4*)dst       = make_float4(num[i][0] * inv, num[i][1] * inv,
                                          num[i][2] * inv, num[i][3] * inv);
        *(float4*)(dst + 4) = make_float4(num[i][4] * inv, num[i][5] * inv,
                                          num[i][6] * inv, num[i][7] * inv);
    }
}

// ---------------------------------------------------------------------------
extern "C" void kernel_launch(void* const* d_in, const int* in_sizes, int n_in,
                              void* d_out, int out_size)
{
    // Size-based input resolution (identity under expected metadata order).
    const float* x = nullptr;
    const float* Ws[4] = {nullptr, nullptr, nullptr, nullptr};
    const float* bs[4] = {nullptr, nullptr, nullptr, nullptr};
    int wi = 0, bi = 0;
    for (int i = 0; i < n_in; i++) {
        const int sz = in_sizes[i];
        if (sz == Mtot * Dm)      { x = (const float*)d_in[i]; }
        else if (sz == Dm * Dm)   { if (wi < 4) Ws[wi++] = (const float*)d_in[i]; }
        else if (sz == Dm)        { if (bi < 4) bs[bi++] = (const float*)d_in[i]; }
    }
    const float* Wq = Ws[0]; const float* bq = bs[0];
    const float* Wk = Ws[1]; const float* bk = bs[1];
    const float* Wv = Ws[2]; const float* bv = bs[2];
    const float* Wo = Ws[3]; const float* bo = bs[3];
    float* out = (float*)d_out;

    // TRUE device addresses of the __device__ globals (the fix: never pass
    // the symbol itself from host — that's the host shadow under ATS).
    float *pq = nullptr, *pk = nullptr, *pv = nullptr, *pa = nullptr;
    cudaGetSymbolAddress((void**)&pq, g_q);
    cudaGetSymbolAddress((void**)&pk, g_k);
    cudaGetSymbolAddress((void**)&pv, g_v);
    cudaGetSymbolAddress((void**)&pa, g_att);

    flag_init_k<<<1, 32>>>();
    check_k<<<1, 256>>>(1, x);                       // code 1: x bad/zero

    const dim3 gg(Dm / 128, Mtot / 128);             // (8, 128)
    gemm_k<1><<<gg, 256>>>(x, Wq, bq, pq);
    gemm_k<1><<<gg, 256>>>(x, Wk, bk, pk);
    gemm_k<2><<<gg, 256>>>(x, Wv, bv, pv);

    check_k<<<1, 256>>>(2, pq);                      // code 2: q unwritten
    check_k<<<1, 256>>>(3, pv);                      // code 3: v unwritten/zero

    chunk_kv_k<<<dim3(Nch, BHn), 256>>>();
    scan_k<<<BHn, 256>>>();
    attn_scores_k<<<dim3(4, Nch, BHn), 256>>>();
    attn_out2_k<<<dim3(Nch, BHn), 256>>>();

    check_k<<<1, 256>>>(4, pa);                      // code 4: attention bad

    gemm_k<0><<<gg, 256>>>(pa, Wo, bo, out);

    check_k<<<1, 256>>>(5, out);                     // code 5: d_out bad
    sig_fill_k<<<2048, 256>>>(out);                  // stage code -> rel_err decade
}

// round 6
// speedup vs baseline: 1.2306x; 1.2306x over previous
#include <cuda_runtime.h>

// ---------------------------------------------------------------------------
// LinearMultiheadAttention: x:(4,4096,1024), 16 heads x 64 dim, chunk 128.
// R6: GEMM rework — split thread tile + warp remap (8tx x 4ty) + padded smem
// (stride 132) + packed fma.rn.f32x2. attn_out also converted to f32x2.
// Globals passed as kernel args MUST go through cudaGetSymbolAddress (ATS!).
// ---------------------------------------------------------------------------

typedef unsigned long long u64;

__device__ __forceinline__ u64 pack2(float x) {
    u64 r;
    asm("mov.b64 %0, {%1, %1};" : "=l"(r) : "f"(x));
    return r;
}
__device__ __forceinline__ u64 ffma2(u64 a, u64 b, u64 c) {
    u64 d;
    asm("fma.rn.f32x2 %0, %1, %2, %3;" : "=l"(d) : "l"(a), "l"(b), "l"(c));
    return d;
}
__device__ __forceinline__ void unpack2(u64 v, float& lo, float& hi) {
    asm("mov.b64 {%0, %1}, %2;" : "=f"(lo), "=f"(hi) : "l"(v));
}

constexpr int Bn   = 4;
constexpr int Sq   = 4096;
constexpr int Dm   = 1024;
constexpr int Hn   = 16;
constexpr int Hd   = 64;
constexpr int Mtot = Bn * Sq;     // 16384
constexpr int Ck   = 128;
constexpr int Nch  = Sq / Ck;     // 32
constexpr int BHn  = Bn * Hn;     // 64

__device__ __align__(16) float g_q[(size_t)Mtot * Dm];
__device__ __align__(16) float g_k[(size_t)Mtot * Dm];
__device__ __align__(16) float g_v[(size_t)Mtot * Dm];
__device__ __align__(16) float g_att[(size_t)Mtot * Dm];
__device__ __align__(16) float g_Sp[(size_t)BHn * Nch * Hd * Hd];
__device__ __align__(16) float g_zp[(size_t)BHn * Nch * Hd];
__device__ __align__(16) float g_sc[(size_t)BHn * Nch * Ck * Ck];

// ---------------------------------------------------------------------------
// GEMM: Y[m,n] = sum_k A[m,k] * W[n,k] + bias[n]
// MODE 0: plain store | MODE 1: phi + permuted [bh][s][hd] | MODE 2: permuted
// 128x128 block, BK=16, 256 threads.
// Thread tile: rows {ty*4+i, 64+ty*4+i}, cols {tx*4+j, 64+tx*4+j} (8x8).
// Warp shape: tx = bits{0..2,7} (8 per warp), ty = bits{3..6} (4 per warp).
// smem stride 132 (conflict reduction + float4 alignment).
// ---------------------------------------------------------------------------
constexpr int SST = 132;

template <int MODE>
__global__ void __launch_bounds__(256, 2)
gemm_k(const float* __restrict__ A, const float* __restrict__ W,
       const float* __restrict__ bias, float* __restrict__ out)
{
    __shared__ __align__(16) float As[16 * SST];
    __shared__ __align__(16) float Bs[16 * SST];

    const int tid = threadIdx.x;
    const int tx  = (tid & 7) | ((tid >> 4) & 8);   // 0..15, 8 per warp
    const int ty  = (tid >> 3) & 15;                // 0..15, 4 per warp
    const int bm  = blockIdx.y << 7;
    const int bn  = blockIdx.x << 7;
    const int lr  = tid >> 2;                        // 0..63 (loader rows)
    const int lc  = (tid & 3) << 2;                  // 0,4,8,12 (loader k)

    const float* Ap = A + (size_t)(bm + lr) * Dm + lc;
    const float* Wp = W + (size_t)(bn + lr) * Dm + lc;

    u64 acc2[8][4];
#pragma unroll
    for (int i = 0; i < 8; i++)
#pragma unroll
        for (int j = 0; j < 4; j++) acc2[i][j] = 0ULL;

    for (int k0 = 0; k0 < Dm; k0 += 16) {
        const float4 a0 = *(const float4*)(Ap + k0);
        const float4 a1 = *(const float4*)(Ap + k0 + (size_t)64 * Dm);
        const float4 b0 = *(const float4*)(Wp + k0);
        const float4 b1 = *(const float4*)(Wp + k0 + (size_t)64 * Dm);
        __syncthreads();
        As[(lc + 0) * SST + lr]      = a0.x; As[(lc + 1) * SST + lr]      = a0.y;
        As[(lc + 2) * SST + lr]      = a0.z; As[(lc + 3) * SST + lr]      = a0.w;
        As[(lc + 0) * SST + lr + 64] = a1.x; As[(lc + 1) * SST + lr + 64] = a1.y;
        As[(lc + 2) * SST + lr + 64] = a1.z; As[(lc + 3) * SST + lr + 64] = a1.w;
        Bs[(lc + 0) * SST + lr]      = b0.x; Bs[(lc + 1) * SST + lr]      = b0.y;
        Bs[(lc + 2) * SST + lr]      = b0.z; Bs[(lc + 3) * SST + lr]      = b0.w;
        Bs[(lc + 0) * SST + lr + 64] = b1.x; Bs[(lc + 1) * SST + lr + 64] = b1.y;
        Bs[(lc + 2) * SST + lr + 64] = b1.z; Bs[(lc + 3) * SST + lr + 64] = b1.w;
        __syncthreads();
#pragma unroll
        for (int kk = 0; kk < 16; kk++) {
            const float4 av0 = *(const float4*)&As[kk * SST + (ty << 2)];
            const float4 av1 = *(const float4*)&As[kk * SST + 64 + (ty << 2)];
            const ulonglong2 bq0 = *(const ulonglong2*)&Bs[kk * SST + (tx << 2)];
            const ulonglong2 bq1 = *(const ulonglong2*)&Bs[kk * SST + 64 + (tx << 2)];
            const u64 b2[4] = {bq0.x, bq0.y, bq1.x, bq1.y};
            const float av[8] = {av0.x, av0.y, av0.z, av0.w,
                                 av1.x, av1.y, av1.z, av1.w};
#pragma unroll
            for (int i = 0; i < 8; i++) {
                const u64 a2 = pack2(av[i]);
#pragma unroll
                for (int j = 0; j < 4; j++)
                    acc2[i][j] = ffma2(a2, b2[j], acc2[i][j]);
            }
        }
    }

    float bv_[8];
    *(float4*)&bv_[0] = *(const float4*)&bias[bn + (tx << 2)];
    *(float4*)&bv_[4] = *(const float4*)&bias[bn + 64 + (tx << 2)];

#pragma unroll
    for (int i = 0; i < 8; i++) {
        const int m = bm + ((i < 4) ? ((ty << 2) + i) : (64 + (ty << 2) + i - 4));
        float y[8];
#pragma unroll
        for (int j = 0; j < 4; j++) unpack2(acc2[i][j], y[2 * j], y[2 * j + 1]);
#pragma unroll
        for (int j = 0; j < 8; j++) {
            float t = y[j] + bv_[j];
            if (MODE == 1) t = (t > 0.f) ? (t + 1.f) : __expf(t);
            y[j] = t;
        }
#pragma unroll
        for (int half = 0; half < 2; half++) {
            const int n0 = bn + half * 64 + (tx << 2);
            float* dst;
            if (MODE == 0) {
                dst = out + (size_t)m * Dm + n0;
            } else {
                const int b  = m >> 12;
                const int s  = m & 4095;
                const int h  = n0 >> 6;
                const int e0 = n0 & 63;
                dst = out + ((size_t)(b * Hn + h) * Sq + s) * Hd + e0;
            }
            *(float4*)dst = make_float4(y[half * 4 + 0], y[half * 4 + 1],
                                        y[half * 4 + 2], y[half * 4 + 3]);
        }
    }
}

// ---------------------------------------------------------------------------
// Per-chunk partials: Sp[bh][c][d][e] = sum_t k[t,d] v[t,e];  zp = sum_t k
// ---------------------------------------------------------------------------
__global__ void __launch_bounds__(256)
chunk_kv_k()
{
    __shared__ __align__(16) float ks[64 * Hd];
    __shared__ __align__(16) float vs[64 * Hd];
    const int c   = blockIdx.x;
    const int bh  = blockIdx.y;
    const int tid = threadIdx.x;
    const size_t base = ((size_t)bh * Sq + (size_t)c * Ck) * Hd;

    const int r  = tid & 63;
    const int j0 = (tid >> 6) << 4;

    float acc[16];
#pragma unroll
    for (int j = 0; j < 16; j++) acc[j] = 0.f;
    float zacc = 0.f;

    for (int half = 0; half < 2; half++) {
        const float4* kg = (const float4*)(g_k + base + (size_t)half * 64 * Hd);
        const float4* vg = (const float4*)(g_v + base + (size_t)half * 64 * Hd);
        __syncthreads();
        for (int i = tid; i < 64 * Hd / 4; i += 256) {
            ((float4*)ks)[i] = kg[i];
            ((float4*)vs)[i] = vg[i];
        }
        __syncthreads();
        for (int t = 0; t < 64; t++) {
            const float kv = ks[t * Hd + r];
            zacc += kv;
#pragma unroll
            for (int j = 0; j < 16; j++)
                acc[j] = fmaf(kv, vs[t * Hd + j0 + j], acc[j]);
        }
    }

    float* Sd = g_Sp + ((size_t)bh * Nch + c) * (Hd * Hd) + r * Hd + j0;
#pragma unroll
    for (int j = 0; j < 16; j++) Sd[j] = acc[j];
    if (tid < Hd) g_zp[((size_t)bh * Nch + c) * Hd + tid] = zacc;
}

// ---------------------------------------------------------------------------
// In-place exclusive prefix over chunks for Sp and zp. grid (BHn).
// ---------------------------------------------------------------------------
__global__ void __launch_bounds__(256)
scan_k()
{
    const int bh = blockIdx.x;
    float* Sb = g_Sp + (size_t)bh * Nch * Hd * Hd;
    for (int e = threadIdx.x; e < Hd * Hd; e += 256) {
        float acc = 0.f;
        for (int c2 = 0; c2 < Nch; c2++) {
            const float v = Sb[(size_t)c2 * Hd * Hd + e];
            Sb[(size_t)c2 * Hd * Hd + e] = acc;
            acc += v;
        }
    }
    if (threadIdx.x < Hd) {
        float* zb = g_zp + (size_t)bh * Nch * Hd + threadIdx.x;
        float acc = 0.f;
        for (int c2 = 0; c2 < Nch; c2++) {
            const float v = zb[(size_t)c2 * Hd];
            zb[(size_t)c2 * Hd] = acc;
            acc += v;
        }
    }
}

// ---------------------------------------------------------------------------
// Masked score tiles. grid (4, Nch, BHn). Tile 3 = fully masked -> zeros.
// ---------------------------------------------------------------------------
__global__ void __launch_bounds__(256)
attn_scores_k()
{
    __shared__ __align__(16) float qT[64][68];
    __shared__ __align__(16) float kT[64][68];
    const int tile = blockIdx.x;
    const int c    = blockIdx.y;
    const int bh   = blockIdx.z;
    const int tid  = threadIdx.x;

    const int lt0 = (tid >> 4) << 2;
    const int lu0 = (tid & 15) << 2;

    if (tile == 3) {
        float* dst = g_sc + (((size_t)bh * Nch + c) * Ck + lt0) * Ck + 64 + lu0;
#pragma unroll
        for (int i = 0; i < 4; i++)
            *(float4*)(dst + (size_t)i * Ck) = make_float4(0.f, 0.f, 0.f, 0.f);
        return;
    }

    const int th = (tile == 0) ? 0 : 1;
    const int uh = (tile == 2) ? 1 : 0;

    const size_t qbase = ((size_t)bh * Sq + (size_t)c * Ck + th * 64) * Hd;
    const size_t kbase = ((size_t)bh * Sq + (size_t)c * Ck + uh * 64) * Hd;

    for (int i = tid; i < 64 * Hd; i += 256) {
        const int t = i >> 6, d = i & 63;
        qT[d][t] = g_q[qbase + i];
        kT[d][t] = g_k[kbase + i];
    }
    __syncthreads();

    float acc[4][4];
#pragma unroll
    for (int i = 0; i < 4; i++)
#pragma unroll
        for (int j = 0; j < 4; j++) acc[i][j] = 0.f;

    for (int d = 0; d < Hd; d++) {
        float a[4], b[4];
        *(float4*)a = *(const float4*)&qT[d][lt0];
        *(float4*)b = *(const float4*)&kT[d][lu0];
#pragma unroll
        for (int i = 0; i < 4; i++)
#pragma unroll
            for (int j = 0; j < 4; j++)
                acc[i][j] = fmaf(a[i], b[j], acc[i][j]);
    }

    const int tg0 = th * 64 + lt0;
    const int ug0 = uh * 64 + lu0;
    float* dst = g_sc + (((size_t)bh * Nch + c) * Ck + tg0) * Ck + ug0;
#pragma unroll
    for (int i = 0; i < 4; i++) {
        float y[4];
#pragma unroll
        for (int j = 0; j < 4; j++)
            y[j] = (ug0 + j <= tg0 + i) ? acc[i][j] : 0.f;
        *(float4*)(dst + (size_t)i * Ck) = make_float4(y[0], y[1], y[2], y[3]);
    }
}

// ---------------------------------------------------------------------------
// Per-chunk output (f32x2). grid (Nch, BHn), 256 threads, 48KB static smem.
// ---------------------------------------------------------------------------
__global__ void __launch_bounds__(256)
attn_out2_k()
{
    __shared__ __align__(16) float vs[Ck][Hd];
    __shared__ __align__(16) float Sx[Hd][Hd];

    const int c   = blockIdx.x;
    const int bh  = blockIdx.y;
    const int tid = threadIdx.x;
    const size_t base = ((size_t)bh * Sq + (size_t)c * Ck) * Hd;

    {
        const float4* vg = (const float4*)(g_v + base);
        for (int i = tid; i < Ck * Hd / 4; i += 256) ((float4*)vs)[i] = vg[i];
        const float4* sg = (const float4*)(g_Sp + ((size_t)bh * Nch + c) * (Hd * Hd));
        for (int i = tid; i < Hd * Hd / 4; i += 256) ((float4*)Sx)[i] = sg[i];
    }
    __syncthreads();

    const int e0 = (tid & 7) << 3;
    const int t0 = (tid >> 3) << 2;

    u64 num2[4][4];
    float rs[4], qz[4];
#pragma unroll
    for (int i = 0; i < 4; i++) {
        rs[i] = 0.f; qz[i] = 0.f;
#pragma unroll
        for (int j = 0; j < 4; j++) num2[i][j] = 0ULL;
    }

    const float* scb = g_sc + ((size_t)bh * Nch + c) * Ck * Ck;
    for (int u4 = 0; u4 < Ck; u4 += 4) {
        float4 sv4[4];
#pragma unroll
        for (int i = 0; i < 4; i++)
            sv4[i] = *(const float4*)&scb[(size_t)(t0 + i) * Ck + u4];
#pragma unroll
        for (int uu = 0; uu < 4; uu++) {
            const int u = u4 + uu;
            const ulonglong2 v01 = *(const ulonglong2*)&vs[u][e0];
            const ulonglong2 v23 = *(const ulonglong2*)&vs[u][e0 + 4];
            const u64 vv2[4] = {v01.x, v01.y, v23.x, v23.y};
#pragma unroll
            for (int i = 0; i < 4; i++) {
                const float* sp = (const float*)&sv4[i];
                const float s = sp[uu];
                rs[i] += s;
                const u64 s2 = pack2(s);
#pragma unroll
                for (int j = 0; j < 4; j++)
                    num2[i][j] = ffma2(s2, vv2[j], num2[i][j]);
            }
        }
    }

    const float* qb = g_q + base;
    const float* zb = g_zp + ((size_t)bh * Nch + c) * Hd;
    for (int d4 = 0; d4 < Hd; d4 += 4) {
        float4 qv4[4];
#pragma unroll
        for (int i = 0; i < 4; i++)
            qv4[i] = *(const float4*)&qb[(size_t)(t0 + i) * Hd + d4];
        const float4 z4 = *(const float4*)&zb[d4];
        const float* zp4 = (const float*)&z4;
#pragma unroll
        for (int dd = 0; dd < 4; dd++) {
            const int d = d4 + dd;
            const float zc = zp4[dd];
            const ulonglong2 s01 = *(const ulonglong2*)&Sx[d][e0];
            const ulonglong2 s23 = *(const ulonglong2*)&Sx[d][e0 + 4];
            const u64 sx2[4] = {s01.x, s01.y, s23.x, s23.y};
#pragma unroll
            for (int i = 0; i < 4; i++) {
                const float* qp = (const float*)&qv4[i];
                const float qv = qp[dd];
                qz[i] = fmaf(qv, zc, qz[i]);
                const u64 q2 = pack2(qv);
#pragma unroll
                for (int j = 0; j < 4; j++)
                    num2[i][j] = ffma2(q2, sx2[j], num2[i][j]);
            }
        }
    }

    const int b = bh >> 4, h = bh & 15;
    float* ob = g_att + ((size_t)b * Sq + (size_t)c * Ck) * Dm + h * Hd + e0;
#pragma unroll
    for (int i = 0; i < 4; i++) {
        const float inv = 1.0f / (rs[i] + qz[i]);
        float y[8];
#pragma unroll
        for (int j = 0; j < 4; j++) unpack2(num2[i][j], y[2 * j], y[2 * j + 1]);
        float* dst = ob + (size_t)(t0 + i) * Dm;
        *(float4*)dst       = make_float4(y[0] * inv, y[1] * inv,
                                          y[2] * inv, y[3] * inv);
        *(float4*)(dst + 4) = make_float4(y[4] * inv, y[5] * inv,
                                          y[6] * inv, y[7] * inv);
    }
}

// ---------------------------------------------------------------------------
extern "C" void kernel_launch(void* const* d_in, const int* in_sizes, int n_in,
                              void* d_out, int out_size)
{
    // Size-based input resolution (identity under expected metadata order).
    const float* x = nullptr;
    const float* Ws[4] = {nullptr, nullptr, nullptr, nullptr};
    const float* bs[4] = {nullptr, nullptr, nullptr, nullptr};
    int wi = 0, bi = 0;
    for (int i = 0; i < n_in; i++) {
        const int sz = in_sizes[i];
        if (sz == Mtot * Dm)      { x = (const float*)d_in[i]; }
        else if (sz == Dm * Dm)   { if (wi < 4) Ws[wi++] = (const float*)d_in[i]; }
        else if (sz == Dm)        { if (bi < 4) bs[bi++] = (const float*)d_in[i]; }
    }
    const float* Wq = Ws[0]; const float* bq = bs[0];
    const float* Wk = Ws[1]; const float* bk = bs[1];
    const float* Wv = Ws[2]; const float* bv = bs[2];
    const float* Wo = Ws[3]; const float* bo = bs[3];
    float* out = (float*)d_out;

    // TRUE device addresses (never pass __device__ symbols from host — ATS!)
    float *pq = nullptr, *pk = nullptr, *pv = nullptr, *pa = nullptr;
    cudaGetSymbolAddress((void**)&pq, g_q);
    cudaGetSymbolAddress((void**)&pk, g_k);
    cudaGetSymbolAddress((void**)&pv, g_v);
    cudaGetSymbolAddress((void**)&pa, g_att);

    const dim3 gg(Dm / 128, Mtot / 128);   // (8, 128)
    gemm_k<1><<<gg, 256>>>(x, Wq, bq, pq);
    gemm_k<1><<<gg, 256>>>(x, Wk, bk, pk);
    gemm_k<2><<<gg, 256>>>(x, Wv, bv, pv);

    chunk_kv_k<<<dim3(Nch, BHn), 256>>>();
    scan_k<<<BHn, 256>>>();
    attn_scores_k<<<dim3(4, Nch, BHn), 256>>>();
    attn_out2_k<<<dim3(Nch, BHn), 256>>>();

    gemm_k<0><<<gg, 256>>>(pa, Wo, bo, out);
}

// round 8
// speedup vs baseline: 1.9375x; 1.5744x over previous
#include <cuda_runtime.h>
#include <cstdint>

// ---------------------------------------------------------------------------
// LinearMultiheadAttention: x:(4,4096,1024), 16 heads x 64 dim, chunk 128.
// R8: tcgen05 is toolchain-blocked (harness targets sm_103 without 'a').
// GEMMs use Ampere-class tensor core path instead: ldmatrix + mma.sync
// m16n8k16 bf16 with split-precision (Y ~= Ah.Bh + Ah.Bl + Al.Bh, fp32 accum).
// Attention mid-section unchanged from R6 (f32x2 SIMT, passing).
// RULE: __device__ symbols passed as kernel args MUST go through
// cudaGetSymbolAddress (GB300 ATS makes the host-shadow silently writable).
// ---------------------------------------------------------------------------

typedef unsigned long long u64;

// ---------------- f32x2 helpers ----------------
__device__ __forceinline__ u64 pack2(float x) {
    u64 r; asm("mov.b64 %0, {%1, %1};" : "=l"(r) : "f"(x)); return r;
}
__device__ __forceinline__ u64 ffma2(u64 a, u64 b, u64 c) {
    u64 d; asm("fma.rn.f32x2 %0, %1, %2, %3;" : "=l"(d) : "l"(a), "l"(b), "l"(c)); return d;
}
__device__ __forceinline__ void unpack2(u64 v, float& lo, float& hi) {
    asm("mov.b64 {%0, %1}, %2;" : "=f"(lo), "=f"(hi) : "l"(v));
}

// ---------------- tensor-core helpers (sm_80 baseline ISA) ----------------
__device__ __forceinline__ uint32_t smem_u32(const void* p) {
    return (uint32_t)__cvta_generic_to_shared(p);
}
__device__ __forceinline__ void ldsm_x4(uint32_t* r, uint32_t addr) {
    asm volatile("ldmatrix.sync.aligned.m8n8.x4.shared.b16 {%0,%1,%2,%3}, [%4];"
                 : "=r"(r[0]), "=r"(r[1]), "=r"(r[2]), "=r"(r[3]) : "r"(addr));
}
__device__ __forceinline__ void ldsm_x2(uint32_t* r, uint32_t addr) {
    asm volatile("ldmatrix.sync.aligned.m8n8.x2.shared.b16 {%0,%1}, [%2];"
                 : "=r"(r[0]), "=r"(r[1]) : "r"(addr));
}
__device__ __forceinline__ void mma_bf16(float* c, const uint32_t* a, const uint32_t* b) {
    asm volatile(
        "mma.sync.aligned.m16n8k16.row.col.f32.bf16.bf16.f32 "
        "{%0,%1,%2,%3}, {%4,%5,%6,%7}, {%8,%9}, {%0,%1,%2,%3};"
        : "+f"(c[0]), "+f"(c[1]), "+f"(c[2]), "+f"(c[3])
        : "r"(a[0]), "r"(a[1]), "r"(a[2]), "r"(a[3]), "r"(b[0]), "r"(b[1]));
}
// 8 fp32 -> 8 bf16 hi (16B) + 8 bf16 lo (16B); element 2i in low half.
__device__ __forceinline__ void cvt8(const float4 f0, const float4 f1,
                                     uint4& hi, uint4& lo)
{
    const float a[8] = {f0.x, f0.y, f0.z, f0.w, f1.x, f1.y, f1.z, f1.w};
    uint32_t h[4], l[4];
#pragma unroll
    for (int i = 0; i < 4; i++) {
        asm("cvt.rn.bf16x2.f32 %0, %1, %2;" : "=r"(h[i]) : "f"(a[2*i+1]), "f"(a[2*i]));
        const float flo = __uint_as_float(h[i] << 16);
        const float fhi = __uint_as_float(h[i] & 0xFFFF0000u);
        asm("cvt.rn.bf16x2.f32 %0, %1, %2;" : "=r"(l[i]) : "f"(a[2*i+1] - fhi), "f"(a[2*i] - flo));
    }
    hi = make_uint4(h[0], h[1], h[2], h[3]);
    lo = make_uint4(l[0], l[1], l[2], l[3]);
}

constexpr int Bn   = 4;
constexpr int Sq   = 4096;
constexpr int Dm   = 1024;
constexpr int Hn   = 16;
constexpr int Hd   = 64;
constexpr int Mtot = Bn * Sq;     // 16384
constexpr int Ck   = 128;
constexpr int Nch  = Sq / Ck;     // 32
constexpr int BHn  = Bn * Hn;     // 64

__device__ __align__(16) float g_q[(size_t)Mtot * Dm];
__device__ __align__(16) float g_k[(size_t)Mtot * Dm];
__device__ __align__(16) float g_v[(size_t)Mtot * Dm];
__device__ __align__(16) float g_att[(size_t)Mtot * Dm];
__device__ __align__(16) float g_Sp[(size_t)BHn * Nch * Hd * Hd];
__device__ __align__(16) float g_zp[(size_t)BHn * Nch * Hd];
__device__ __align__(16) float g_sc[(size_t)BHn * Nch * Ck * Ck];

// ---------------------------------------------------------------------------
// HMMA GEMM: Y[m,n] = sum_k A[m,k]*W[n,k] + bias[n]
// MODE 0: plain store | MODE 1: phi + permuted [bh][s][hd] | MODE 2: permuted
// 128x128 tile, BK=32, 8 warps (2m x 4n), warp tile 64x32 (4x4 m16n8k16).
// Split-precision bf16: 3 MMAs per logical fp32 product.
// ---------------------------------------------------------------------------
constexpr int BK  = 32;
constexpr int LDK = 40;   // padded smem row (bf16 elems): 80B stride, LDSM conflict-free

template <int MODE>
__global__ void __launch_bounds__(256, 2)
hmma_gemm_k(const float* __restrict__ A, const float* __restrict__ W,
            const float* __restrict__ bias, float* __restrict__ out)
{
    __shared__ __align__(16) uint16_t Ah[128 * LDK];
    __shared__ __align__(16) uint16_t Al[128 * LDK];
    __shared__ __align__(16) uint16_t Bh[128 * LDK];
    __shared__ __align__(16) uint16_t Bl[128 * LDK];

    const int tid  = threadIdx.x;
    const int lane = tid & 31;
    const int wid  = tid >> 5;
    const int wm   = wid >> 2;          // 0..1  (m offset wm*64)
    const int wn   = wid & 3;           // 0..3  (n offset wn*32)
    const int bm   = blockIdx.y << 7;
    const int bn   = blockIdx.x << 7;

    // loaders: each thread owns one row-half (16 k-elems)
    const int lrow  = tid >> 1;
    const int lhalf = (tid & 1) << 4;   // 0 or 16
    const float* Ar = A + (size_t)(bm + lrow) * Dm + lhalf;
    const float* Wr = W + (size_t)(bn + lrow) * Dm + lhalf;
    const uint32_t sbyte = (uint32_t)(lrow * LDK + lhalf) * 2;

    float acc[4][4][4];
#pragma unroll
    for (int i = 0; i < 4; i++)
#pragma unroll
        for (int j = 0; j < 4; j++)
#pragma unroll
            for (int r = 0; r < 4; r++) acc[i][j][r] = 0.f;

    const uint32_t aB = smem_u32(Ah), alB = smem_u32(Al);
    const uint32_t bB = smem_u32(Bh), blB = smem_u32(Bl);

    for (int kc = 0; kc < Dm / BK; kc++) {
        if (kc) __syncthreads();
        {
            uint4 hi, lo;
            cvt8(*(const float4*)(Ar + kc * BK),
                 *(const float4*)(Ar + kc * BK + 4), hi, lo);
            *(uint4*)((char*)Ah + sbyte)      = hi;
            *(uint4*)((char*)Al + sbyte)      = lo;
            cvt8(*(const float4*)(Ar + kc * BK + 8),
                 *(const float4*)(Ar + kc * BK + 12), hi, lo);
            *(uint4*)((char*)Ah + sbyte + 16) = hi;
            *(uint4*)((char*)Al + sbyte + 16) = lo;
            cvt8(*(const float4*)(Wr + kc * BK),
                 *(const float4*)(Wr + kc * BK + 4), hi, lo);
            *(uint4*)((char*)Bh + sbyte)      = hi;
            *(uint4*)((char*)Bl + sbyte)      = lo;
            cvt8(*(const float4*)(Wr + kc * BK + 8),
                 *(const float4*)(Wr + kc * BK + 12), hi, lo);
            *(uint4*)((char*)Bh + sbyte + 16) = hi;
            *(uint4*)((char*)Bl + sbyte + 16) = lo;
        }
        __syncthreads();

#pragma unroll
        for (int ks = 0; ks < BK; ks += 16) {
            // B fragments for all 4 n-atoms (hi & lo)
            uint32_t bh_[4][2], bl_[4][2];
            const uint32_t brow = (uint32_t)(wn * 32 + (lane & 7));
            const uint32_t bk_  = (uint32_t)(ks + ((lane >> 3) & 1) * 8);
#pragma unroll
            for (int an = 0; an < 4; an++) {
                const uint32_t off = ((brow + an * 8) * LDK + bk_) * 2;
                ldsm_x2(bh_[an], bB + off);
                ldsm_x2(bl_[an], blB + off);
            }
            const uint32_t arow = (uint32_t)(wm * 64 + (lane & 15));
            const uint32_t ak_  = (uint32_t)(ks + (lane >> 4) * 8);
#pragma unroll
            for (int am = 0; am < 4; am++) {
                uint32_t ah_[4], al_[4];
                const uint32_t off = ((arow + am * 16) * LDK + ak_) * 2;
                ldsm_x4(ah_, aB + off);
                ldsm_x4(al_, alB + off);
#pragma unroll
                for (int an = 0; an < 4; an++) {
                    mma_bf16(acc[am][an], ah_, bh_[an]);
                    mma_bf16(acc[am][an], ah_, bl_[an]);
                    mma_bf16(acc[am][an], al_, bh_[an]);
                }
            }
        }
    }

    // Epilogue: fragment layout c0/c1 -> (row, col..col+1), c2/c3 -> row+8.
    const int fr = lane >> 2;            // 0..7
    const int fc = (lane & 3) << 1;      // 0,2,4,6
#pragma unroll
    for (int am = 0; am < 4; am++) {
        const int m0 = bm + wm * 64 + am * 16 + fr;
#pragma unroll
        for (int an = 0; an < 4; an++) {
            const int c = bn + wn * 32 + an * 8 + fc;
            const float b0 = bias[c], b1 = bias[c + 1];
#pragma unroll
            for (int half = 0; half < 2; half++) {
                const int m = m0 + half * 8;
                float y0 = acc[am][an][2 * half]     + b0;
                float y1 = acc[am][an][2 * half + 1] + b1;
                if (MODE == 1) {
                    y0 = (y0 > 0.f) ? (y0 + 1.f) : __expf(y0);
                    y1 = (y1 > 0.f) ? (y1 + 1.f) : __expf(y1);
                }
                float* dst;
                if (MODE == 0) {
                    dst = out + (size_t)m * Dm + c;
                } else {
                    const int b  = m >> 12;
                    const int s  = m & 4095;
                    const int h  = c >> 6;
                    const int e0 = c & 63;
                    dst = out + ((size_t)(b * Hn + h) * Sq + s) * Hd + e0;
                }
                *(float2*)dst = make_float2(y0, y1);
            }
        }
    }
}

// ---------------------------------------------------------------------------
// Per-chunk partials: Sp[bh][c][d][e] = sum_t k[t,d] v[t,e];  zp = sum_t k
// ---------------------------------------------------------------------------
__global__ void __launch_bounds__(256)
chunk_kv_k()
{
    __shared__ __align__(16) float ks[64 * Hd];
    __shared__ __align__(16) float vs[64 * Hd];
    const int c   = blockIdx.x;
    const int bh  = blockIdx.y;
    const int tid = threadIdx.x;
    const size_t base = ((size_t)bh * Sq + (size_t)c * Ck) * Hd;

    const int r  = tid & 63;
    const int j0 = (tid >> 6) << 4;

    float acc[16];
#pragma unroll
    for (int j = 0; j < 16; j++) acc[j] = 0.f;
    float zacc = 0.f;

    for (int half = 0; half < 2; half++) {
        const float4* kg = (const float4*)(g_k + base + (size_t)half * 64 * Hd);
        const float4* vg = (const float4*)(g_v + base + (size_t)half * 64 * Hd);
        __syncthreads();
        for (int i = tid; i < 64 * Hd / 4; i += 256) {
            ((float4*)ks)[i] = kg[i];
            ((float4*)vs)[i] = vg[i];
        }
        __syncthreads();
        for (int t = 0; t < 64; t++) {
            const float kv = ks[t * Hd + r];
            zacc += kv;
#pragma unroll
            for (int j = 0; j < 16; j++)
                acc[j] = fmaf(kv, vs[t * Hd + j0 + j], acc[j]);
        }
    }

    float* Sd = g_Sp + ((size_t)bh * Nch + c) * (Hd * Hd) + r * Hd + j0;
#pragma unroll
    for (int j = 0; j < 16; j++) Sd[j] = acc[j];
    if (tid < Hd) g_zp[((size_t)bh * Nch + c) * Hd + tid] = zacc;
}

// ---------------------------------------------------------------------------
__global__ void __launch_bounds__(256)
scan_k()
{
    const int bh = blockIdx.x;
    float* Sb = g_Sp + (size_t)bh * Nch * Hd * Hd;
    for (int e = threadIdx.x; e < Hd * Hd; e += 256) {
        float acc = 0.f;
        for (int c2 = 0; c2 < Nch; c2++) {
            const float v = Sb[(size_t)c2 * Hd * Hd + e];
            Sb[(size_t)c2 * Hd * Hd + e] = acc;
            acc += v;
        }
    }
    if (threadIdx.x < Hd) {
        float* zb = g_zp + (size_t)bh * Nch * Hd + threadIdx.x;
        float acc = 0.f;
        for (int c2 = 0; c2 < Nch; c2++) {
            const float v = zb[(size_t)c2 * Hd];
            zb[(size_t)c2 * Hd] = acc;
            acc += v;
        }
    }
}

// ---------------------------------------------------------------------------
// Masked score tiles. grid (4, Nch, BHn). Tile 3 = fully masked -> zeros.
// ---------------------------------------------------------------------------
__global__ void __launch_bounds__(256)
attn_scores_k()
{
    __shared__ __align__(16) float qT[64][68];
    __shared__ __align__(16) float kT[64][68];
    const int tile = blockIdx.x;
    const int c    = blockIdx.y;
    const int bh   = blockIdx.z;
    const int tid  = threadIdx.x;

    const int lt0 = (tid >> 4) << 2;
    const int lu0 = (tid & 15) << 2;

    if (tile == 3) {
        float* dst = g_sc + (((size_t)bh * Nch + c) * Ck + lt0) * Ck + 64 + lu0;
#pragma unroll
        for (int i = 0; i < 4; i++)
            *(float4*)(dst + (size_t)i * Ck) = make_float4(0.f, 0.f, 0.f, 0.f);
        return;
    }

    const int th = (tile == 0) ? 0 : 1;
    const int uh = (tile == 2) ? 1 : 0;

    const size_t qbase = ((size_t)bh * Sq + (size_t)c * Ck + th * 64) * Hd;
    const size_t kbase = ((size_t)bh * Sq + (size_t)c * Ck + uh * 64) * Hd;

    for (int i = tid; i < 64 * Hd; i += 256) {
        const int t = i >> 6, d = i & 63;
        qT[d][t] = g_q[qbase + i];
        kT[d][t] = g_k[kbase + i];
    }
    __syncthreads();

    float acc[4][4];
#pragma unroll
    for (int i = 0; i < 4; i++)
#pragma unroll
        for (int j = 0; j < 4; j++) acc[i][j] = 0.f;

    for (int d = 0; d < Hd; d++) {
        float a[4], b[4];
        *(float4*)a = *(const float4*)&qT[d][lt0];
        *(float4*)b = *(const float4*)&kT[d][lu0];
#pragma unroll
        for (int i = 0; i < 4; i++)
#pragma unroll
            for (int j = 0; j < 4; j++)
                acc[i][j] = fmaf(a[i], b[j], acc[i][j]);
    }

    const int tg0 = th * 64 + lt0;
    const int ug0 = uh * 64 + lu0;
    float* dst = g_sc + (((size_t)bh * Nch + c) * Ck + tg0) * Ck + ug0;
#pragma unroll
    for (int i = 0; i < 4; i++) {
        float y[4];
#pragma unroll
        for (int j = 0; j < 4; j++)
            y[j] = (ug0 + j <= tg0 + i) ? acc[i][j] : 0.f;
        *(float4*)(dst + (size_t)i * Ck) = make_float4(y[0], y[1], y[2], y[3]);
    }
}

// ---------------------------------------------------------------------------
// Per-chunk output (f32x2). grid (Nch, BHn), 256 threads, 48KB static smem.
// ---------------------------------------------------------------------------
__global__ void __launch_bounds__(256)
attn_out2_k()
{
    __shared__ __align__(16) float vs[Ck][Hd];
    __shared__ __align__(16) float Sx[Hd][Hd];

    const int c   = blockIdx.x;
    const int bh  = blockIdx.y;
    const int tid = threadIdx.x;
    const size_t base = ((size_t)bh * Sq + (size_t)c * Ck) * Hd;

    {
        const float4* vg = (const float4*)(g_v + base);
        for (int i = tid; i < Ck * Hd / 4; i += 256) ((float4*)vs)[i] = vg[i];
        const float4* sg = (const float4*)(g_Sp + ((size_t)bh * Nch + c) * (Hd * Hd));
        for (int i = tid; i < Hd * Hd / 4; i += 256) ((float4*)Sx)[i] = sg[i];
    }
    __syncthreads();

    const int e0 = (tid & 7) << 3;
    const int t0 = (tid >> 3) << 2;

    u64 num2[4][4];
    float rs[4], qz[4];
#pragma unroll
    for (int i = 0; i < 4; i++) {
        rs[i] = 0.f; qz[i] = 0.f;
#pragma unroll
        for (int j = 0; j < 4; j++) num2[i][j] = 0ULL;
    }

    const float* scb = g_sc + ((size_t)bh * Nch + c) * Ck * Ck;
    for (int u4 = 0; u4 < Ck; u4 += 4) {
        float4 sv4[4];
#pragma unroll
        for (int i = 0; i < 4; i++)
            sv4[i] = *(const float4*)&scb[(size_t)(t0 + i) * Ck + u4];
#pragma unroll
        for (int uu = 0; uu < 4; uu++) {
            const int u = u4 + uu;
            const ulonglong2 v01 = *(const ulonglong2*)&vs[u][e0];
            const ulonglong2 v23 = *(const ulonglong2*)&vs[u][e0 + 4];
            const u64 vv2[4] = {v01.x, v01.y, v23.x, v23.y};
#pragma unroll
            for (int i = 0; i < 4; i++) {
                const float* sp = (const float*)&sv4[i];
                const float s = sp[uu];
                rs[i] += s;
                const u64 s2 = pack2(s);
#pragma unroll
                for (int j = 0; j < 4; j++)
                    num2[i][j] = ffma2(s2, vv2[j], num2[i][j]);
            }
        }
    }

    const float* qb = g_q + base;
    const float* zb = g_zp + ((size_t)bh * Nch + c) * Hd;
    for (int d4 = 0; d4 < Hd; d4 += 4) {
        float4 qv4[4];
#pragma unroll
        for (int i = 0; i < 4; i++)
            qv4[i] = *(const float4*)&qb[(size_t)(t0 + i) * Hd + d4];
        const float4 z4 = *(const float4*)&zb[d4];
        const float* zp4 = (const float*)&z4;
#pragma unroll
        for (int dd = 0; dd < 4; dd++) {
            const int d = d4 + dd;
            const float zc = zp4[dd];
            const ulonglong2 s01 = *(const ulonglong2*)&Sx[d][e0];
            const ulonglong2 s23 = *(const ulonglong2*)&Sx[d][e0 + 4];
            const u64 sx2[4] = {s01.x, s01.y, s23.x, s23.y};
#pragma unroll
            for (int i = 0; i < 4; i++) {
                const float* qp = (const float*)&qv4[i];
                const float qv = qp[dd];
                qz[i] = fmaf(qv, zc, qz[i]);
                const u64 q2 = pack2(qv);
#pragma unroll
                for (int j = 0; j < 4; j++)
                    num2[i][j] = ffma2(q2, sx2[j], num2[i][j]);
            }
        }
    }

    const int b = bh >> 4, h = bh & 15;
    float* ob = g_att + ((size_t)b * Sq + (size_t)c * Ck) * Dm + h * Hd + e0;
#pragma unroll
    for (int i = 0; i < 4; i++) {
        const float inv = 1.0f / (rs[i] + qz[i]);
        float y[8];
#pragma unroll
        for (int j = 0; j < 4; j++) unpack2(num2[i][j], y[2 * j], y[2 * j + 1]);
        float* dst = ob + (size_t)(t0 + i) * Dm;
        *(float4*)dst       = make_float4(y[0] * inv, y[1] * inv,
                                          y[2] * inv, y[3] * inv);
        *(float4*)(dst + 4) = make_float4(y[4] * inv, y[5] * inv,
                                          y[6] * inv, y[7] * inv);
    }
}

// ---------------------------------------------------------------------------
extern "C" void kernel_launch(void* const* d_in, const int* in_sizes, int n_in,
                              void* d_out, int out_size)
{
    // Size-based input resolution (identity under expected metadata order).
    const float* x = nullptr;
    const float* Ws[4] = {nullptr, nullptr, nullptr, nullptr};
    const float* bs[4] = {nullptr, nullptr, nullptr, nullptr};
    int wi = 0, bi = 0;
    for (int i = 0; i < n_in; i++) {
        const int sz = in_sizes[i];
        if (sz == Mtot * Dm)      { x = (const float*)d_in[i]; }
        else if (sz == Dm * Dm)   { if (wi < 4) Ws[wi++] = (const float*)d_in[i]; }
        else if (sz == Dm)        { if (bi < 4) bs[bi++] = (const float*)d_in[i]; }
    }
    const float* Wq = Ws[0]; const float* bq = bs[0];
    const float* Wk = Ws[1]; const float* bk = bs[1];
    const float* Wv = Ws[2]; const float* bv = bs[2];
    const float* Wo = Ws[3]; const float* bo = bs[3];
    float* out = (float*)d_out;

    // TRUE device addresses (never pass __device__ symbols from host — ATS!)
    float *pq = nullptr, *pk = nullptr, *pv = nullptr, *pa = nullptr;
    cudaGetSymbolAddress((void**)&pq, g_q);
    cudaGetSymbolAddress((void**)&pk, g_k);
    cudaGetSymbolAddress((void**)&pv, g_v);
    cudaGetSymbolAddress((void**)&pa, g_att);

    const dim3 gg(Dm / 128, Mtot / 128);   // (8, 128)
    hmma_gemm_k<1><<<gg, 256>>>(x, Wq, bq, pq);
    hmma_gemm_k<1><<<gg, 256>>>(x, Wk, bk, pk);
    hmma_gemm_k<2><<<gg, 256>>>(x, Wv, bv, pv);

    chunk_kv_k<<<dim3(Nch, BHn), 256>>>();
    scan_k<<<BHn, 256>>>();
    attn_scores_k<<<dim3(4, Nch, BHn), 256>>>();
    attn_out2_k<<<dim3(Nch, BHn), 256>>>();

    hmma_gemm_k<0><<<gg, 256>>>(pa, Wo, bo, out);
}